// round 11
// baseline (speedup 1.0000x reference)
#include <cuda_runtime.h>

// PersistenceLandscapeEncoder: pairs (32768,2) f32 -> landscapes (5,4096) f32.
//
// tent_i(t) = min(t-b_i, d_i-t) clamped at 0.  With m=(b+d)/2:
//   m <  t  ->  value = d - t ;  m >= t -> value = t - b
// Buckets ALIGNED to the t-grid (4096).  Column j:
//   top5 = merge( {prefixTop5d(buckets<j) - t}+ , {t - suffixBot5b(buckets>=j)}+ )
//
// SINGLE kernel, 16 blocks x 256 threads, 3 generation barriers:
//   P0 minmax (pairs -> registers)      P1 aligned scatter (from registers)
//   P2 warp-per-group fine lists -> SMEM (only group totals -> global)
//   P3 coarse scan (SMEM, 2 block syncs)  P4 columns (pure SMEM + 1 gather)
// All cross-block reads use __ldcg (no launch boundary => no L1 invalidate).
// Replay-safe: g_count reset in P2; g_amin/g_amax reset in P2 (read in P1).

#define N_PAIRS 32768
#define RES     4096
#define NB      4096
#define CAP     64
#define NGROUP  128          // NB / 32
#define GRID1   16
#define TPB     256
#define NEGINF  (-3.0e38f)
#define POSINF  (3.0e38f)

__device__ unsigned g_amin = 0xFFFFFFFFu;   // ordered-uint encodings
__device__ unsigned g_amax = 0u;
__device__ int    g_count[NB];              // zero-init; reset in P2
__device__ float2 g_slab[NB * CAP];
__device__ float  g_GT[NGROUP][5];          // group total top-5 d (desc)
__device__ float  g_GB[NGROUP][5];          // group total bot-5 b (asc)
__device__ int           g_barcnt = 0;
__device__ volatile int  g_bargen = 0;

__device__ __forceinline__ unsigned enc(float f) {
    int i = __float_as_int(f);
    return (unsigned)(i ^ ((i >> 31) | 0x80000000));
}
__device__ __forceinline__ float dec(unsigned u) {
    int i = (u & 0x80000000u) ? (int)(u ^ 0x80000000u) : ~(int)u;
    return __int_as_float(i);
}

__device__ __forceinline__ void grid_barrier16() {
    __syncthreads();
    if (threadIdx.x == 0) {
        int gen = g_bargen;
        __threadfence();
        if (atomicAdd(&g_barcnt, 1) == GRID1 - 1) {
            g_barcnt = 0;
            __threadfence();
            g_bargen = gen + 1;
        } else {
            while (g_bargen == gen) { }
        }
    }
    __syncthreads();
}

// ---- sorted 5-list networks (static indices only) --------------------------
__device__ __forceinline__ void merge_desc(
    float& a0, float& a1, float& a2, float& a3, float& a4,
    float b0, float b1, float b2, float b3, float b4)
{
    float m0 = fmaxf(a0, b0);
    float m1 = fmaxf(fmaxf(a1, b1), fminf(a0, b0));
    float m2 = fmaxf(fmaxf(a2, b2), fmaxf(fminf(a0, b1), fminf(a1, b0)));
    float m3 = fmaxf(fmaxf(a3, b3),
               fmaxf(fminf(a0, b2), fmaxf(fminf(a1, b1), fminf(a2, b0))));
    float m4 = fmaxf(fmaxf(a4, b4),
               fmaxf(fmaxf(fminf(a0, b3), fminf(a1, b2)),
                     fmaxf(fminf(a2, b1), fminf(a3, b0))));
    a0 = m0; a1 = m1; a2 = m2; a3 = m3; a4 = m4;
}

__device__ __forceinline__ void merge_asc(
    float& a0, float& a1, float& a2, float& a3, float& a4,
    float b0, float b1, float b2, float b3, float b4)
{
    float m0 = fminf(a0, b0);
    float m1 = fminf(fminf(a1, b1), fmaxf(a0, b0));
    float m2 = fminf(fminf(a2, b2), fminf(fmaxf(a0, b1), fmaxf(a1, b0)));
    float m3 = fminf(fminf(a3, b3),
               fminf(fmaxf(a0, b2), fminf(fmaxf(a1, b1), fmaxf(a2, b0))));
    float m4 = fminf(fminf(a4, b4),
               fminf(fminf(fmaxf(a0, b3), fmaxf(a1, b2)),
                     fminf(fmaxf(a2, b1), fmaxf(a3, b0))));
    a0 = m0; a1 = m1; a2 = m2; a3 = m3; a4 = m4;
}

__device__ __forceinline__ void insert_desc(
    float& t0, float& t1, float& t2, float& t3, float& t4, float v)
{
    if (v > t4) {
        t4 = v;
        if (t4 > t3) { float x = t4; t4 = t3; t3 = x;
          if (t3 > t2) { x = t3; t3 = t2; t2 = x;
            if (t2 > t1) { x = t2; t2 = t1; t1 = x;
              if (t1 > t0) { x = t1; t1 = t0; t0 = x; }
            }
          }
        }
    }
}

__device__ __forceinline__ void insert_asc(
    float& t0, float& t1, float& t2, float& t3, float& t4, float v)
{
    if (v < t4) {
        t4 = v;
        if (t4 < t3) { float x = t4; t4 = t3; t3 = x;
          if (t3 < t2) { x = t3; t3 = t2; t2 = x;
            if (t2 < t1) { x = t2; t2 = t1; t1 = x;
              if (t1 < t0) { x = t1; t1 = t0; t0 = x; }
            }
          }
        }
    }
}

// ---------------------------------------------------------------------------
__global__ void __launch_bounds__(TPB) fused_kernel(
    const float2* __restrict__ pairs, float* __restrict__ out)
{
    __shared__ float smn[8], smx[8];
    __shared__ float sPfx[8][32][5], sSfx[8][32][5];   // fine lists (block-local)
    __shared__ float sPc[NGROUP][5], sSc[NGROUP][5];   // coarse scan
    __shared__ float wtP[4][5], wtS[4][5];

    const int tid  = threadIdx.x;
    const int warp = tid >> 5;
    const int lane = tid & 31;
    const int gtid = blockIdx.x * TPB + tid;           // 0..4095

    // ===== P0: minmax; keep 4 float4 (8 pairs) in registers =====
    float4 v[4];
    {
        const float4* p4 = (const float4*)pairs;       // 16384 float4 total
        #pragma unroll
        for (int i = 0; i < 4; i++) v[i] = p4[gtid + i * (GRID1 * TPB)];

        float mn = POSINF, mx = NEGINF;
        #pragma unroll
        for (int i = 0; i < 4; i++) {
            mn = fminf(mn, fminf(v[i].x, v[i].z));
            mx = fmaxf(mx, fmaxf(v[i].y, v[i].w));
        }
        #pragma unroll
        for (int off = 16; off >= 1; off >>= 1) {
            mn = fminf(mn, __shfl_xor_sync(0xffffffffu, mn, off));
            mx = fmaxf(mx, __shfl_xor_sync(0xffffffffu, mx, off));
        }
        if (lane == 0) { smn[warp] = mn; smx[warp] = mx; }
        __syncthreads();
        if (tid < 8) {
            mn = smn[tid]; mx = smx[tid];
            #pragma unroll
            for (int off = 4; off >= 1; off >>= 1) {
                mn = fminf(mn, __shfl_xor_sync(0xffu, mn, off));
                mx = fmaxf(mx, __shfl_xor_sync(0xffu, mx, off));
            }
            if (tid == 0) {
                atomicMin(&g_amin, enc(mn));
                atomicMax(&g_amax, enc(mx));
            }
        }
    }
    grid_barrier16();

    // grid params (cross-block -> ldcg)
    const float tmin = dec(__ldcg(&g_amin));
    const float tmax = dec(__ldcg(&g_amax));
    const float span = fmaxf(tmax - tmin, 1e-30f);
    const float scale = (float)(RES - 1) / span;
    const float dt    = span / (float)(RES - 1);

    // ===== P1: aligned scatter from registers =====
    #pragma unroll
    for (int i = 0; i < 4; i++) {
        float m0 = 0.5f * (v[i].x + v[i].y);
        int b0i = min(NB - 1, max(0, (int)((m0 - tmin) * scale)));
        int pos0 = atomicAdd(&g_count[b0i], 1);
        if (pos0 < CAP) g_slab[b0i * CAP + pos0] = make_float2(v[i].x, v[i].y);

        float m1 = 0.5f * (v[i].z + v[i].w);
        int b1i = min(NB - 1, max(0, (int)((m1 - tmin) * scale)));
        int pos1 = atomicAdd(&g_count[b1i], 1);
        if (pos1 < CAP) g_slab[b1i * CAP + pos1] = make_float2(v[i].z, v[i].w);
    }
    grid_barrier16();

    // ===== P2: warp per group -> fine lists in SMEM, totals to global =====
    {
        const int grp = blockIdx.x * 8 + warp;         // 0..127
        const int bkt = grp * 32 + lane;

        float d0=NEGINF,d1=NEGINF,d2=NEGINF,d3=NEGINF,d4=NEGINF;
        float b0=POSINF,b1=POSINF,b2=POSINF,b3=POSINF,b4=POSINF;
        const int n = min(__ldcg(&g_count[bkt]), CAP);
        g_count[bkt] = 0;                              // replay-safe reset
        const float2* s = &g_slab[bkt * CAP];
        for (int k = 0; k < n; k++) {
            float2 p = __ldcg(&s[k]);
            insert_desc(d0, d1, d2, d3, d4, p.y);
            insert_asc (b0, b1, b2, b3, b4, p.x);
        }

        // inclusive prefix scan of deaths (desc)
        float i0=d0, i1=d1, i2=d2, i3=d3, i4=d4;
        #pragma unroll
        for (int off = 1; off < 32; off <<= 1) {
            float e0 = __shfl_up_sync(0xffffffffu, i0, off);
            float e1 = __shfl_up_sync(0xffffffffu, i1, off);
            float e2 = __shfl_up_sync(0xffffffffu, i2, off);
            float e3 = __shfl_up_sync(0xffffffffu, i3, off);
            float e4 = __shfl_up_sync(0xffffffffu, i4, off);
            if (lane >= off) merge_desc(i0,i1,i2,i3,i4, e0,e1,e2,e3,e4);
        }
        float p0 = __shfl_up_sync(0xffffffffu, i0, 1);
        float p1 = __shfl_up_sync(0xffffffffu, i1, 1);
        float p2 = __shfl_up_sync(0xffffffffu, i2, 1);
        float p3 = __shfl_up_sync(0xffffffffu, i3, 1);
        float p4 = __shfl_up_sync(0xffffffffu, i4, 1);
        if (lane == 0) { p0=NEGINF; p1=NEGINF; p2=NEGINF; p3=NEGINF; p4=NEGINF; }
        sPfx[warp][lane][0]=p0; sPfx[warp][lane][1]=p1; sPfx[warp][lane][2]=p2;
        sPfx[warp][lane][3]=p3; sPfx[warp][lane][4]=p4;
        if (lane == 31) {
            g_GT[grp][0]=i0; g_GT[grp][1]=i1; g_GT[grp][2]=i2;
            g_GT[grp][3]=i3; g_GT[grp][4]=i4;
        }

        // inclusive suffix scan of births (asc)
        float u0=b0, u1=b1, u2=b2, u3=b3, u4=b4;
        #pragma unroll
        for (int off = 1; off < 32; off <<= 1) {
            float e0 = __shfl_down_sync(0xffffffffu, u0, off);
            float e1 = __shfl_down_sync(0xffffffffu, u1, off);
            float e2 = __shfl_down_sync(0xffffffffu, u2, off);
            float e3 = __shfl_down_sync(0xffffffffu, u3, off);
            float e4 = __shfl_down_sync(0xffffffffu, u4, off);
            if (lane + off < 32) merge_asc(u0,u1,u2,u3,u4, e0,e1,e2,e3,e4);
        }
        sSfx[warp][lane][0]=u0; sSfx[warp][lane][1]=u1; sSfx[warp][lane][2]=u2;
        sSfx[warp][lane][3]=u3; sSfx[warp][lane][4]=u4;
        if (lane == 0) {
            g_GB[grp][0]=u0; g_GB[grp][1]=u1; g_GB[grp][2]=u2;
            g_GB[grp][3]=u3; g_GB[grp][4]=u4;
        }
    }
    // replay-safe reset (all blocks consumed g_amin/g_amax before barrier 2)
    if (blockIdx.x == 0 && tid == 0) {
        g_amin = 0xFFFFFFFFu;
        g_amax = 0u;
    }
    grid_barrier16();

    // ===== P3: coarse scan over 128 group totals (2 block syncs) =====
    if (tid < NGROUP) {
        const int g = tid, w = tid >> 5, l = tid & 31;
        float a0=NEGINF,a1=NEGINF,a2=NEGINF,a3=NEGINF,a4=NEGINF;
        if (g > 0) {
            a0=__ldcg(&g_GT[g-1][0]); a1=__ldcg(&g_GT[g-1][1]);
            a2=__ldcg(&g_GT[g-1][2]); a3=__ldcg(&g_GT[g-1][3]);
            a4=__ldcg(&g_GT[g-1][4]);
        }
        #pragma unroll
        for (int off = 1; off < 32; off <<= 1) {
            float e0 = __shfl_up_sync(0xffffffffu, a0, off);
            float e1 = __shfl_up_sync(0xffffffffu, a1, off);
            float e2 = __shfl_up_sync(0xffffffffu, a2, off);
            float e3 = __shfl_up_sync(0xffffffffu, a3, off);
            float e4 = __shfl_up_sync(0xffffffffu, a4, off);
            if (l >= off) merge_desc(a0,a1,a2,a3,a4, e0,e1,e2,e3,e4);
        }
        if (l == 31) { wtP[w][0]=a0; wtP[w][1]=a1; wtP[w][2]=a2;
                       wtP[w][3]=a3; wtP[w][4]=a4; }
        sPc[g][0]=a0; sPc[g][1]=a1; sPc[g][2]=a2; sPc[g][3]=a3; sPc[g][4]=a4;
    } else {
        const int g = tid - NGROUP, w = g >> 5, l = g & 31;
        float a0=POSINF,a1=POSINF,a2=POSINF,a3=POSINF,a4=POSINF;
        if (g < NGROUP - 1) {
            a0=__ldcg(&g_GB[g+1][0]); a1=__ldcg(&g_GB[g+1][1]);
            a2=__ldcg(&g_GB[g+1][2]); a3=__ldcg(&g_GB[g+1][3]);
            a4=__ldcg(&g_GB[g+1][4]);
        }
        #pragma unroll
        for (int off = 1; off < 32; off <<= 1) {
            float e0 = __shfl_down_sync(0xffffffffu, a0, off);
            float e1 = __shfl_down_sync(0xffffffffu, a1, off);
            float e2 = __shfl_down_sync(0xffffffffu, a2, off);
            float e3 = __shfl_down_sync(0xffffffffu, a3, off);
            float e4 = __shfl_down_sync(0xffffffffu, a4, off);
            if (l + off < 32) merge_asc(a0,a1,a2,a3,a4, e0,e1,e2,e3,e4);
        }
        if (l == 0) { wtS[w][0]=a0; wtS[w][1]=a1; wtS[w][2]=a2;
                      wtS[w][3]=a3; wtS[w][4]=a4; }
        sSc[g][0]=a0; sSc[g][1]=a1; sSc[g][2]=a2; sSc[g][3]=a3; sSc[g][4]=a4;
    }
    __syncthreads();

    if (tid < NGROUP) {
        const int g = tid, w = tid >> 5;
        if (w > 0) {
            float a0=sPc[g][0], a1=sPc[g][1], a2=sPc[g][2],
                  a3=sPc[g][3], a4=sPc[g][4];
            #pragma unroll
            for (int q = 0; q < 3; q++)
                if (q < w)
                    merge_desc(a0,a1,a2,a3,a4,
                               wtP[q][0], wtP[q][1], wtP[q][2], wtP[q][3], wtP[q][4]);
            sPc[g][0]=a0; sPc[g][1]=a1; sPc[g][2]=a2; sPc[g][3]=a3; sPc[g][4]=a4;
        }
    } else {
        const int g = tid - NGROUP, w = g >> 5;
        if (w < 3) {
            float a0=sSc[g][0], a1=sSc[g][1], a2=sSc[g][2],
                  a3=sSc[g][3], a4=sSc[g][4];
            #pragma unroll
            for (int q = 1; q < 4; q++)
                if (q > w)
                    merge_asc(a0,a1,a2,a3,a4,
                              wtS[q][0], wtS[q][1], wtS[q][2], wtS[q][3], wtS[q][4]);
            sSc[g][0]=a0; sSc[g][1]=a1; sSc[g][2]=a2; sSc[g][3]=a3; sSc[g][4]=a4;
        }
    }
    __syncthreads();

    // ===== P4: 256 columns per block, fine lists from SMEM =====
    {
        const int j = blockIdx.x * 256 + tid;          // column 0..4095
        const float t = tmin + (float)j * dt;
        const int g = blockIdx.x * 8 + warp;           // column j's group

        float p0=sPfx[warp][lane][0], p1=sPfx[warp][lane][1],
              p2=sPfx[warp][lane][2], p3=sPfx[warp][lane][3],
              p4=sPfx[warp][lane][4];
        merge_desc(p0,p1,p2,p3,p4,
                   sPc[g][0], sPc[g][1], sPc[g][2], sPc[g][3], sPc[g][4]);

        float s0=sSfx[warp][lane][0], s1=sSfx[warp][lane][1],
              s2=sSfx[warp][lane][2], s3=sSfx[warp][lane][3],
              s4=sSfx[warp][lane][4];
        merge_asc(s0,s1,s2,s3,s4,
                  sSc[g][0], sSc[g][1], sSc[g][2], sSc[g][3], sSc[g][4]);

        p0 = fmaxf(p0 - t, 0.0f); p1 = fmaxf(p1 - t, 0.0f); p2 = fmaxf(p2 - t, 0.0f);
        p3 = fmaxf(p3 - t, 0.0f); p4 = fmaxf(p4 - t, 0.0f);
        float q0 = fmaxf(t - s0, 0.0f), q1 = fmaxf(t - s1, 0.0f);
        float q2 = fmaxf(t - s2, 0.0f), q3 = fmaxf(t - s3, 0.0f);
        float q4 = fmaxf(t - s4, 0.0f);
        merge_desc(p0,p1,p2,p3,p4, q0,q1,q2,q3,q4);

        out[0 * RES + j] = p0;
        out[1 * RES + j] = p1;
        out[2 * RES + j] = p2;
        out[3 * RES + j] = p3;
        out[4 * RES + j] = p4;
    }
}

extern "C" void kernel_launch(void* const* d_in, const int* in_sizes, int n_in,
                              void* d_out, int out_size) {
    const float2* pairs = (const float2*)d_in[0];
    float* out = (float*)d_out;
    fused_kernel<<<GRID1, TPB>>>(pairs, out);
}

// round 12
// speedup vs baseline: 1.7210x; 1.7210x over previous
#include <cuda_runtime.h>

// PersistenceLandscapeEncoder: pairs (32768,2) f32 -> landscapes (5,4096) f32.
//
// tent_i(t) = min(t-b_i, d_i-t) clamped at 0.  With m=(b+d)/2:
//   m <  t  ->  value = d - t ;  m >= t -> value = t - b
// Buckets ALIGNED to the t-grid (4096).  Column j:
//   top5 = merge( {prefixTop5d(buckets<j) - t}+ , {t - suffixBot5b(buckets>=j)}+ )
//
// 4 launches (R7's measured-fast kernels), chained with PROGRAMMATIC DEPENDENT
// LAUNCH: consumers ramp + run their independent preamble under the producer's
// tail, then cudaGridDependencySynchronize() before dependent reads.
//   K1 minmax (atomic encoded)     K2 scatter (pairs preloaded pre-sync)
//   K3 warp-per-group fine scans   K4 coarse scan + columns
// Replay-safe: g_count reset in K3; g_amin/g_amax reset in K4 tail.

#define N_PAIRS 32768
#define RES     4096
#define NB      4096
#define CAP     64
#define NGROUP  128          // NB / 32
#define NEGINF  (-3.0e38f)
#define POSINF  (3.0e38f)

__device__ unsigned g_amin = 0xFFFFFFFFu;   // ordered-uint encodings
__device__ unsigned g_amax = 0u;
__device__ float  g_tmin, g_dt;
__device__ int    g_count[NB];              // zero-init; K3 re-zeroes
__device__ float2 g_slab[NB * CAP];
__device__ float4 g_Pf4[NB];  __device__ float g_Pf1[NB];  // excl prefix top5 d
__device__ float4 g_Sf4[NB];  __device__ float g_Sf1[NB];  // incl suffix bot5 b
__device__ float  g_GT[NGROUP][5];   // group total top-5 d (desc)
__device__ float  g_GB[NGROUP][5];   // group total bot-5 b (asc)

__device__ __forceinline__ unsigned enc(float f) {
    int i = __float_as_int(f);
    return (unsigned)(i ^ ((i >> 31) | 0x80000000));
}
__device__ __forceinline__ float dec(unsigned u) {
    int i = (u & 0x80000000u) ? (int)(u ^ 0x80000000u) : ~(int)u;
    return __int_as_float(i);
}

// ---- sorted 5-list networks (static indices only) --------------------------
__device__ __forceinline__ void merge_desc(
    float& a0, float& a1, float& a2, float& a3, float& a4,
    float b0, float b1, float b2, float b3, float b4)
{
    float m0 = fmaxf(a0, b0);
    float m1 = fmaxf(fmaxf(a1, b1), fminf(a0, b0));
    float m2 = fmaxf(fmaxf(a2, b2), fmaxf(fminf(a0, b1), fminf(a1, b0)));
    float m3 = fmaxf(fmaxf(a3, b3),
               fmaxf(fminf(a0, b2), fmaxf(fminf(a1, b1), fminf(a2, b0))));
    float m4 = fmaxf(fmaxf(a4, b4),
               fmaxf(fmaxf(fminf(a0, b3), fminf(a1, b2)),
                     fmaxf(fminf(a2, b1), fminf(a3, b0))));
    a0 = m0; a1 = m1; a2 = m2; a3 = m3; a4 = m4;
}

__device__ __forceinline__ void merge_asc(
    float& a0, float& a1, float& a2, float& a3, float& a4,
    float b0, float b1, float b2, float b3, float b4)
{
    float m0 = fminf(a0, b0);
    float m1 = fminf(fminf(a1, b1), fmaxf(a0, b0));
    float m2 = fminf(fminf(a2, b2), fminf(fmaxf(a0, b1), fmaxf(a1, b0)));
    float m3 = fminf(fminf(a3, b3),
               fminf(fmaxf(a0, b2), fminf(fmaxf(a1, b1), fmaxf(a2, b0))));
    float m4 = fminf(fminf(a4, b4),
               fminf(fminf(fmaxf(a0, b3), fmaxf(a1, b2)),
                     fminf(fmaxf(a2, b1), fmaxf(a3, b0))));
    a0 = m0; a1 = m1; a2 = m2; a3 = m3; a4 = m4;
}

__device__ __forceinline__ void insert_desc(
    float& t0, float& t1, float& t2, float& t3, float& t4, float v)
{
    if (v > t4) {
        t4 = v;
        if (t4 > t3) { float x = t4; t4 = t3; t3 = x;
          if (t3 > t2) { x = t3; t3 = t2; t2 = x;
            if (t2 > t1) { x = t2; t2 = t1; t1 = x;
              if (t1 > t0) { x = t1; t1 = t0; t0 = x; }
            }
          }
        }
    }
}

__device__ __forceinline__ void insert_asc(
    float& t0, float& t1, float& t2, float& t3, float& t4, float v)
{
    if (v < t4) {
        t4 = v;
        if (t4 < t3) { float x = t4; t4 = t3; t3 = x;
          if (t3 < t2) { x = t3; t3 = t2; t2 = x;
            if (t2 < t1) { x = t2; t2 = t1; t1 = x;
              if (t1 < t0) { x = t1; t1 = t0; t0 = x; }
            }
          }
        }
    }
}

// ---------------------------------------------------------------------------
// K1: wide minmax -> atomic encoded min/max.
// ---------------------------------------------------------------------------
__global__ void __launch_bounds__(256) minmax_kernel(const float2* __restrict__ pairs) {
    __shared__ float smn[8], smx[8];
    const int tid = threadIdx.x;
    const float4 v = ((const float4*)pairs)[blockIdx.x * 256 + tid];  // (b,d,b,d)
    float mn = fminf(v.x, v.z);
    float mx = fmaxf(v.y, v.w);
    #pragma unroll
    for (int off = 16; off >= 1; off >>= 1) {
        mn = fminf(mn, __shfl_xor_sync(0xffffffffu, mn, off));
        mx = fmaxf(mx, __shfl_xor_sync(0xffffffffu, mx, off));
    }
    if ((tid & 31) == 0) { smn[tid >> 5] = mn; smx[tid >> 5] = mx; }
    __syncthreads();
    if (tid < 8) {
        mn = smn[tid]; mx = smx[tid];
        #pragma unroll
        for (int off = 4; off >= 1; off >>= 1) {
            mn = fminf(mn, __shfl_xor_sync(0xffu, mn, off));
            mx = fmaxf(mx, __shfl_xor_sync(0xffu, mx, off));
        }
        if (tid == 0) {
            atomicMin(&g_amin, enc(mn));
            atomicMax(&g_amax, enc(mx));
        }
    }
}

// ---------------------------------------------------------------------------
// K2: scatter.  PDL: load pairs + midpoints BEFORE grid sync (independent).
// ---------------------------------------------------------------------------
__global__ void __launch_bounds__(256) scatter_kernel(const float2* __restrict__ pairs) {
    const int i = blockIdx.x * 256 + threadIdx.x;
    const float4 v = ((const float4*)pairs)[i];            // independent preamble
    const float m0 = 0.5f * (v.x + v.y);
    const float m1 = 0.5f * (v.z + v.w);

    cudaGridDependencySynchronize();                       // wait for minmax

    const float tmin = dec(g_amin);
    const float tmax = dec(g_amax);
    const float span = fmaxf(tmax - tmin, 1e-30f);
    const float scale = (float)(RES - 1) / span;
    if (i == 0) {
        g_tmin = tmin;
        g_dt   = span / (float)(RES - 1);
    }
    int b0i = min(NB - 1, max(0, (int)((m0 - tmin) * scale)));
    int pos0 = atomicAdd(&g_count[b0i], 1);
    if (pos0 < CAP) g_slab[b0i * CAP + pos0] = make_float2(v.x, v.y);

    int b1i = min(NB - 1, max(0, (int)((m1 - tmin) * scale)));
    int pos1 = atomicAdd(&g_count[b1i], 1);
    if (pos1 < CAP) g_slab[b1i * CAP + pos1] = make_float2(v.z, v.w);
}

// ---------------------------------------------------------------------------
// K3: warp per 32-bucket group: fine lists + shfl scans.  Resets g_count.
// ---------------------------------------------------------------------------
__global__ void __launch_bounds__(256) group_kernel() {
    cudaGridDependencySynchronize();                       // ramp overlapped

    const int warp = (blockIdx.x * 256 + threadIdx.x) >> 5;  // group 0..127
    const int lane = threadIdx.x & 31;
    const int bkt  = warp * 32 + lane;

    float d0=NEGINF,d1=NEGINF,d2=NEGINF,d3=NEGINF,d4=NEGINF;
    float b0=POSINF,b1=POSINF,b2=POSINF,b3=POSINF,b4=POSINF;
    const int n = min(g_count[bkt], CAP);
    g_count[bkt] = 0;                       // replay-safe reset (sole toucher)
    const float2* s = &g_slab[bkt * CAP];
    for (int k = 0; k < n; k++) {
        float2 p = s[k];
        insert_desc(d0, d1, d2, d3, d4, p.y);
        insert_asc (b0, b1, b2, b3, b4, p.x);
    }

    // inclusive prefix scan of deaths (desc)
    float i0=d0, i1=d1, i2=d2, i3=d3, i4=d4;
    #pragma unroll
    for (int off = 1; off < 32; off <<= 1) {
        float e0 = __shfl_up_sync(0xffffffffu, i0, off);
        float e1 = __shfl_up_sync(0xffffffffu, i1, off);
        float e2 = __shfl_up_sync(0xffffffffu, i2, off);
        float e3 = __shfl_up_sync(0xffffffffu, i3, off);
        float e4 = __shfl_up_sync(0xffffffffu, i4, off);
        if (lane >= off) merge_desc(i0,i1,i2,i3,i4, e0,e1,e2,e3,e4);
    }
    float p0 = __shfl_up_sync(0xffffffffu, i0, 1);
    float p1 = __shfl_up_sync(0xffffffffu, i1, 1);
    float p2 = __shfl_up_sync(0xffffffffu, i2, 1);
    float p3 = __shfl_up_sync(0xffffffffu, i3, 1);
    float p4 = __shfl_up_sync(0xffffffffu, i4, 1);
    if (lane == 0) { p0=NEGINF; p1=NEGINF; p2=NEGINF; p3=NEGINF; p4=NEGINF; }
    g_Pf4[bkt] = make_float4(p0, p1, p2, p3);
    g_Pf1[bkt] = p4;
    if (lane == 31) {
        g_GT[warp][0]=i0; g_GT[warp][1]=i1; g_GT[warp][2]=i2;
        g_GT[warp][3]=i3; g_GT[warp][4]=i4;
    }

    // inclusive suffix scan of births (asc)
    float u0=b0, u1=b1, u2=b2, u3=b3, u4=b4;
    #pragma unroll
    for (int off = 1; off < 32; off <<= 1) {
        float e0 = __shfl_down_sync(0xffffffffu, u0, off);
        float e1 = __shfl_down_sync(0xffffffffu, u1, off);
        float e2 = __shfl_down_sync(0xffffffffu, u2, off);
        float e3 = __shfl_down_sync(0xffffffffu, u3, off);
        float e4 = __shfl_down_sync(0xffffffffu, u4, off);
        if (lane + off < 32) merge_asc(u0,u1,u2,u3,u4, e0,e1,e2,e3,e4);
    }
    g_Sf4[bkt] = make_float4(u0, u1, u2, u3);
    g_Sf1[bkt] = u4;
    if (lane == 0) {
        g_GB[warp][0]=u0; g_GB[warp][1]=u1; g_GB[warp][2]=u2;
        g_GB[warp][3]=u3; g_GB[warp][4]=u4;
    }
}

// ---------------------------------------------------------------------------
// K4: 8 blocks x 512: warp-hierarchical coarse scan (2 barriers) + columns.
// ---------------------------------------------------------------------------
__global__ void __launch_bounds__(512) landscape_kernel(float* __restrict__ out)
{
    __shared__ float sPc[NGROUP][5], sSc[NGROUP][5];
    __shared__ float wtP[4][5], wtS[4][5];
    const int tid = threadIdx.x;

    cudaGridDependencySynchronize();                       // ramp overlapped

    if (tid < NGROUP) {
        // prefix side: scan shifted GT (A'[g] = GT[g-1])
        const int g = tid, w = tid >> 5, lane = tid & 31;
        float a0=NEGINF,a1=NEGINF,a2=NEGINF,a3=NEGINF,a4=NEGINF;
        if (g > 0) { a0=g_GT[g-1][0]; a1=g_GT[g-1][1]; a2=g_GT[g-1][2];
                     a3=g_GT[g-1][3]; a4=g_GT[g-1][4]; }
        #pragma unroll
        for (int off = 1; off < 32; off <<= 1) {
            float e0 = __shfl_up_sync(0xffffffffu, a0, off);
            float e1 = __shfl_up_sync(0xffffffffu, a1, off);
            float e2 = __shfl_up_sync(0xffffffffu, a2, off);
            float e3 = __shfl_up_sync(0xffffffffu, a3, off);
            float e4 = __shfl_up_sync(0xffffffffu, a4, off);
            if (lane >= off) merge_desc(a0,a1,a2,a3,a4, e0,e1,e2,e3,e4);
        }
        if (lane == 31) { wtP[w][0]=a0; wtP[w][1]=a1; wtP[w][2]=a2;
                          wtP[w][3]=a3; wtP[w][4]=a4; }
        sPc[g][0]=a0; sPc[g][1]=a1; sPc[g][2]=a2; sPc[g][3]=a3; sPc[g][4]=a4;
    } else if (tid < 2 * NGROUP) {
        // suffix side: scan shifted GB (A''[g] = GB[g+1])
        const int g = tid - NGROUP, w = g >> 5, lane = g & 31;
        float a0=POSINF,a1=POSINF,a2=POSINF,a3=POSINF,a4=POSINF;
        if (g < NGROUP - 1) { a0=g_GB[g+1][0]; a1=g_GB[g+1][1]; a2=g_GB[g+1][2];
                              a3=g_GB[g+1][3]; a4=g_GB[g+1][4]; }
        #pragma unroll
        for (int off = 1; off < 32; off <<= 1) {
            float e0 = __shfl_down_sync(0xffffffffu, a0, off);
            float e1 = __shfl_down_sync(0xffffffffu, a1, off);
            float e2 = __shfl_down_sync(0xffffffffu, a2, off);
            float e3 = __shfl_down_sync(0xffffffffu, a3, off);
            float e4 = __shfl_down_sync(0xffffffffu, a4, off);
            if (lane + off < 32) merge_asc(a0,a1,a2,a3,a4, e0,e1,e2,e3,e4);
        }
        if (lane == 0) { wtS[w][0]=a0; wtS[w][1]=a1; wtS[w][2]=a2;
                         wtS[w][3]=a3; wtS[w][4]=a4; }
        sSc[g][0]=a0; sSc[g][1]=a1; sSc[g][2]=a2; sSc[g][3]=a3; sSc[g][4]=a4;
    }
    __syncthreads();

    if (tid < NGROUP) {
        const int g = tid, w = tid >> 5;
        if (w > 0) {
            float a0=sPc[g][0], a1=sPc[g][1], a2=sPc[g][2],
                  a3=sPc[g][3], a4=sPc[g][4];
            #pragma unroll
            for (int q = 0; q < 3; q++)
                if (q < w)
                    merge_desc(a0,a1,a2,a3,a4,
                               wtP[q][0], wtP[q][1], wtP[q][2], wtP[q][3], wtP[q][4]);
            sPc[g][0]=a0; sPc[g][1]=a1; sPc[g][2]=a2; sPc[g][3]=a3; sPc[g][4]=a4;
        }
    } else if (tid < 2 * NGROUP) {
        const int g = tid - NGROUP, w = g >> 5;
        if (w < 3) {
            float a0=sSc[g][0], a1=sSc[g][1], a2=sSc[g][2],
                  a3=sSc[g][3], a4=sSc[g][4];
            #pragma unroll
            for (int q = 1; q < 4; q++)
                if (q > w)
                    merge_asc(a0,a1,a2,a3,a4,
                              wtS[q][0], wtS[q][1], wtS[q][2], wtS[q][3], wtS[q][4]);
            sSc[g][0]=a0; sSc[g][1]=a1; sSc[g][2]=a2; sSc[g][3]=a3; sSc[g][4]=a4;
        }
    }
    __syncthreads();

    // per-column assembly
    const int j = blockIdx.x * 512 + tid;          // column 0..4095
    const float t = g_tmin + (float)j * g_dt;
    const int g = j >> 5;

    float4 pf = g_Pf4[j]; float pf4 = g_Pf1[j];
    float p0=pf.x, p1=pf.y, p2=pf.z, p3=pf.w, p4=pf4;
    merge_desc(p0,p1,p2,p3,p4,
               sPc[g][0], sPc[g][1], sPc[g][2], sPc[g][3], sPc[g][4]);

    float4 sf = g_Sf4[j]; float sf4 = g_Sf1[j];
    float s0=sf.x, s1=sf.y, s2=sf.z, s3=sf.w, s4=sf4;
    merge_asc(s0,s1,s2,s3,s4,
              sSc[g][0], sSc[g][1], sSc[g][2], sSc[g][3], sSc[g][4]);

    p0 = fmaxf(p0 - t, 0.0f); p1 = fmaxf(p1 - t, 0.0f); p2 = fmaxf(p2 - t, 0.0f);
    p3 = fmaxf(p3 - t, 0.0f); p4 = fmaxf(p4 - t, 0.0f);
    float q0 = fmaxf(t - s0, 0.0f), q1 = fmaxf(t - s1, 0.0f);
    float q2 = fmaxf(t - s2, 0.0f), q3 = fmaxf(t - s3, 0.0f);
    float q4 = fmaxf(t - s4, 0.0f);
    merge_desc(p0,p1,p2,p3,p4, q0,q1,q2,q3,q4);

    out[0 * RES + j] = p0;
    out[1 * RES + j] = p1;
    out[2 * RES + j] = p2;
    out[3 * RES + j] = p3;
    out[4 * RES + j] = p4;

    // replay-safe reset of the atomic minmax (K2 consumed them this run)
    if (blockIdx.x == 0 && tid == 0) {
        g_amin = 0xFFFFFFFFu;
        g_amax = 0u;
    }
}

// ---------------------------------------------------------------------------
template <typename F, typename... Args>
static void launch_pdl(F kernel, dim3 grid, dim3 block, Args... args) {
    cudaLaunchConfig_t cfg = {};
    cfg.gridDim = grid;
    cfg.blockDim = block;
    cfg.dynamicSmemBytes = 0;
    cfg.stream = 0;                       // legacy default stream (captured)
    cudaLaunchAttribute attr[1];
    attr[0].id = cudaLaunchAttributeProgrammaticStreamSerialization;
    attr[0].val.programmaticStreamSerializationAllowed = 1;
    cfg.attrs = attr;
    cfg.numAttrs = 1;
    cudaLaunchKernelEx(&cfg, kernel, args...);
}

extern "C" void kernel_launch(void* const* d_in, const int* in_sizes, int n_in,
                              void* d_out, int out_size) {
    const float2* pairs = (const float2*)d_in[0];
    float* out = (float*)d_out;

    minmax_kernel<<<N_PAIRS / 2 / 256, 256>>>(pairs);              // 64 blocks
    launch_pdl(scatter_kernel,   dim3(N_PAIRS / 2 / 256), dim3(256), pairs);
    launch_pdl(group_kernel,     dim3(NB / 32 / 8),       dim3(256));
    launch_pdl(landscape_kernel, dim3(RES / 512),         dim3(512), out);
}